// round 16
// baseline (speedup 1.0000x reference)
#include <cuda_runtime.h>
#include <cstdint>

#define B_ 2
#define N_ 1024
#define D_ 128
#define H_ 64

// Scratch (no allocations allowed).
__device__ float g_ai[B_ * N_ * H_];     // [b][n][h] (only active n written)
__device__ float g_ajbTc[B_ * H_ * N_];  // [b][h][jc] column-compacted
__device__ int   g_jlist[B_ * N_];       // [b][jc] -> original j
__device__ int   g_nact[B_];             // active column count per batch

// ---- cp.async helpers ----
__device__ __forceinline__ void cp_async16(void* s, const void* g) {
    uint32_t su = (uint32_t)__cvta_generic_to_shared(s);
    asm volatile("cp.async.cg.shared.global [%0], [%1], 16;" :: "r"(su), "l"(g));
}
#define CP_COMMIT() asm volatile("cp.async.commit_group;" ::: "memory")
#define CP_WAIT1()  asm volatile("cp.async.wait_group 1;" ::: "memory")

// ---------------------------------------------------------------------------
// Compact: jlist = active j's ascending; nact per batch; also zero-pads the
// ajbTc tail columns [nact, npad) for all h (pass1c never writes them).
// Grid = B_, 1024 threads.
// ---------------------------------------------------------------------------
__global__ __launch_bounds__(1024) void compact_kernel(const int* __restrict__ visited)
{
    __shared__ int warpTot[32], warpOff[32];
    __shared__ int s_nact;
    const int b = blockIdx.x;
    const int tid = threadIdx.x;
    const int lane = tid & 31, w = tid >> 5;

    const bool act = (visited[b * N_ + tid] == 0);
    const unsigned mask = __ballot_sync(0xffffffffu, act);
    const int rank = __popc(mask & ((1u << lane) - 1u));
    if (lane == 0) warpTot[w] = __popc(mask);
    __syncthreads();
    if (w == 0) {
        int v = warpTot[lane];
        int s = v;
#pragma unroll
        for (int o = 1; o < 32; o <<= 1) {
            int x = __shfl_up_sync(0xffffffffu, s, o);
            if (lane >= o) s += x;
        }
        warpOff[lane] = s - v;
        if (lane == 31) { g_nact[b] = s; s_nact = s; }
    }
    __syncthreads();
    if (act) g_jlist[b * N_ + warpOff[w] + rank] = tid;

    // Zero-pad tail columns of the compacted matrix.
    const int nact = s_nact;
    const int npad = (nact + 127) & ~127;
    const int pad = npad - nact;
    for (int k = tid; k < pad * H_; k += 1024) {
        int h = k / pad, jc = nact + (k % pad);
        g_ajbTc[(b * H_ + h) * N_ + jc] = 0.f;
    }
}

// ---------------------------------------------------------------------------
// Pass 1 over ACTIVE nodes only (compacted index space): for idx < nact,
// n = jlist[idx]:  ai[n] = E[n] @ Wi^T ;  ajbTc[h][idx] = E[n] @ Wj^T + b1.
// Visited nodes need neither (row -> uniform, column -> masked) — half the
// work skipped; gather kernel eliminated (direct compacted write).
// Grid = B*N/8 = 256 blocks (blocks past nact exit immediately), 256 thr.
// ---------------------------------------------------------------------------
__global__ __launch_bounds__(256) void pass1c_kernel(
    const float* __restrict__ E, const float* __restrict__ W1,
    const float* __restrict__ b1)
{
    __shared__ float Esh[8][32];
    __shared__ float Wc[32][132];
    __shared__ int nsh[8];

    const int tid = threadIdx.x;
    const int b = blockIdx.x >> 7;
    const int idx0 = (blockIdx.x & 127) * 8;
    const int nact = g_nact[b];
    if (idx0 >= nact) return;                 // whole block inactive

    const int r = tid >> 5;
    const int ob = (tid & 31) * 4;
    const int idx = idx0 + r;
    if (tid < 8) {
        int ii = idx0 + tid;
        nsh[tid] = g_jlist[b * N_ + ((ii < nact) ? ii : (nact - 1))];  // clamp
    }
    __syncthreads();
    const int n = nsh[r];

    float acc[4] = {0.f, 0.f, 0.f, 0.f};

    for (int dc = 0; dc < D_; dc += 32) {
        __syncthreads();
        {
            int rr = tid >> 5, dd = tid & 31;
            Esh[rr][dd] = E[(b * N_ + nsh[rr]) * D_ + dc + dd];
        }
#pragma unroll
        for (int k = tid; k < 32 * 128; k += 256) {
            int o = k >> 5, dd = k & 31;
            float v = (o < H_) ? W1[o * (2 * D_) + dc + dd]
                               : W1[(o - H_) * (2 * D_) + D_ + dc + dd];
            Wc[dd][o] = v;
        }
        __syncthreads();
#pragma unroll
        for (int dd = 0; dd < 32; dd++) {
            const float e = Esh[r][dd];                     // warp broadcast
            const float4 w4 = *(const float4*)&Wc[dd][ob];  // conflict-free
            acc[0] += e * w4.x;  acc[1] += e * w4.y;
            acc[2] += e * w4.z;  acc[3] += e * w4.w;
        }
    }

    if (idx < nact) {                          // guard partial blocks
        if (ob < H_) {
            *(float4*)&g_ai[(b * N_ + n) * H_ + ob] =
                make_float4(acc[0], acc[1], acc[2], acc[3]);
        } else {
            const int h0 = ob - H_;
#pragma unroll
            for (int k = 0; k < 4; k++)
                g_ajbTc[(b * H_ + h0 + k) * N_ + idx] = acc[k] + b1[h0 + k];
        }
    }
}

// ---------------------------------------------------------------------------
// Pass 2 (unchanged — proven 20.7us): compacted columns + cp.async
// double-buffered half-tile pipeline; in-register softmax; scatter via jlist.
// Grid = B*N/8 = 256 blocks, 256 thr = 8 warps, warp w owns row i_base+w.
// ---------------------------------------------------------------------------
__global__ __launch_bounds__(256) void pass2_kernel(
    const int* __restrict__ visited,
    const float* __restrict__ W2, const float* __restrict__ b2,
    float* __restrict__ out)
{
    __shared__ float buf[2][32][128];       // 32 KB
    __shared__ float2 pk[8][H_];            // 4 KB: (ai[i], w2[h])

    const int tid = threadIdx.x;
    const int w = tid >> 5, lane = tid & 31;
    const int b = blockIdx.x >> 7;
    const int i_base = (blockIdx.x & 127) * 8;
    const int i = i_base + w;

    const int nact = g_nact[b];
    const int T = (nact + 127) >> 7;
    const int C = 2 * T;                    // block-uniform chunk count
    const float* base = &g_ajbTc[(b * H_) * N_];

#pragma unroll
    for (int k = tid; k < 8 * H_; k += 256) {
        int wi = k >> 6, h = k & 63;
        pk[wi][h] = make_float2(g_ai[(b * N_ + i_base + wi) * H_ + h], W2[h]);
    }

    const bool vi = visited[b * N_ + i] != 0;      // warp-uniform
    float* orow = out + (size_t)(b * N_ + i) * N_;
    if (vi) {
        const float4 uni = make_float4(1.f / N_, 1.f / N_, 1.f / N_, 1.f / N_);
#pragma unroll
        for (int t = 0; t < 8; t++) *(float4*)&orow[t * 128 + lane * 4] = uni;
    } else {
        const float4 z = make_float4(0.f, 0.f, 0.f, 0.f);
#pragma unroll
        for (int t = 0; t < 8; t++) *(float4*)&orow[t * 128 + lane * 4] = z;
    }

    // Prologue: stage chunk 0 (tile 0, h 0..31) into buf[0].
    if (C > 0) {
#pragma unroll
        for (int r = 0; r < 4; r++) {
            int k = tid + r * 256;
            int h = k >> 5, c4 = k & 31;
            cp_async16(&buf[0][h][c4 * 4], base + h * N_ + c4 * 4);
        }
    }
    CP_COMMIT();

    float a[8][4] = {};

#pragma unroll
    for (int c = 0; c < 16; c++) {
        if (c < C) {                               // block-uniform
            __syncthreads();                       // chunk c-1 compute done
            if (c + 1 < C) {
                const int t1 = (c + 1) >> 1, hh1 = ((c + 1) & 1) * 32;
                float (*nb)[128] = buf[(c + 1) & 1];
                const float* src = base + t1 * 128 + hh1 * N_;
#pragma unroll
                for (int r = 0; r < 4; r++) {
                    int k = tid + r * 256;
                    int h = k >> 5, c4 = k & 31;
                    cp_async16(&nb[h][c4 * 4], src + h * N_ + c4 * 4);
                }
            }
            CP_COMMIT();
            CP_WAIT1();                            // chunk c complete
            __syncthreads();

            if (!vi) {
                const int t = c >> 1, hh = (c & 1) * 32;
                const float (*cb)[128] = buf[c & 1];
                float s0 = 0.f, s1 = 0.f, s2 = 0.f, s3 = 0.f;
#pragma unroll 8
                for (int h = 0; h < 32; h++) {
                    const float2 cc = pk[w][hh + h];              // LDS.64 bcast
                    const float4 v = *(const float4*)&cb[h][lane * 4];
                    s0 += fmaxf(cc.x + v.x, 0.f) * cc.y;
                    s1 += fmaxf(cc.x + v.y, 0.f) * cc.y;
                    s2 += fmaxf(cc.x + v.z, 0.f) * cc.y;
                    s3 += fmaxf(cc.x + v.w, 0.f) * cc.y;
                }
                a[t][0] += s0; a[t][1] += s1; a[t][2] += s2; a[t][3] += s3;
            }
        }
    }

    if (vi) return;

    // ---- softmax over active columns (jc < nact), in registers ----
    const float bb = b2[0];
    float m = -3.4e38f;
#pragma unroll
    for (int t = 0; t < 8; t++)
#pragma unroll
        for (int k = 0; k < 4; k++) {
            const int jc = t * 128 + lane * 4 + k;
            float e = (jc < nact) ? (a[t][k] + bb) : -1.0e9f;
            a[t][k] = e;
            m = fmaxf(m, e);
        }
#pragma unroll
    for (int o = 16; o > 0; o >>= 1)
        m = fmaxf(m, __shfl_xor_sync(0xffffffffu, m, o));

    float sum = 0.f;
#pragma unroll
    for (int t = 0; t < 8; t++)
#pragma unroll
        for (int k = 0; k < 4; k++) {
            const float p = __expf(a[t][k] - m);
            a[t][k] = p; sum += p;
        }
#pragma unroll
    for (int o = 16; o > 0; o >>= 1)
        sum += __shfl_xor_sync(0xffffffffu, sum, o);

    const float inv = 1.f / sum;
    const int* jl = &g_jlist[b * N_];              // L1-cached reads
#pragma unroll
    for (int t = 0; t < 8; t++)
#pragma unroll
        for (int k = 0; k < 4; k++) {
            const int jc = t * 128 + lane * 4 + k;
            if (jc < nact) orow[jl[jc]] = a[t][k] * inv;
        }
}

extern "C" void kernel_launch(void* const* d_in, const int* in_sizes, int n_in,
                              void* d_out, int out_size) {
    const float* E  = (const float*)d_in[0];
    const int* vis  = (const int*)d_in[1];   // jax bool -> int32 in harness
    // d_in[2] = remaining_capacity: unused by the reference.
    const float* W1 = (const float*)d_in[3];
    const float* b1 = (const float*)d_in[4];
    const float* W2 = (const float*)d_in[5];
    const float* b2 = (const float*)d_in[6];
    float* out      = (float*)d_out;

    compact_kernel<<<B_, 1024>>>(vis);
    pass1c_kernel<<<B_ * (N_ / 8), 256>>>(E, W1, b1);
    pass2_kernel<<<B_ * (N_ / 8), 256>>>(vis, W2, b2, out);
}

// round 17
// speedup vs baseline: 1.7162x; 1.7162x over previous
#include <cuda_runtime.h>
#include <cstdint>

#define B_ 2
#define N_ 1024
#define D_ 128
#define H_ 64

// Scratch (no allocations allowed).
__device__ float g_ai[B_ * N_ * H_];     // [b][n][h] (only active n written)
__device__ float g_ajbTc[B_ * H_ * N_];  // [b][h][jc] column-compacted

// ---- cp.async helpers ----
__device__ __forceinline__ void cp_async16(void* s, const void* g) {
    uint32_t su = (uint32_t)__cvta_generic_to_shared(s);
    asm volatile("cp.async.cg.shared.global [%0], [%1], 16;" :: "r"(su), "l"(g));
}
#define CP_COMMIT() asm volatile("cp.async.commit_group;" ::: "memory")
#define CP_WAIT1()  asm volatile("cp.async.wait_group 1;" ::: "memory")

// ---------------------------------------------------------------------------
// Block-local compaction (256 threads over 1024 entries): fills jl_sh with
// ascending active indices, returns nact. One int4 LDG per thread + popc
// scan; ~30 instr, 2 barriers. Replaces the serial grid-2 compact kernel.
// ---------------------------------------------------------------------------
__device__ __forceinline__ int block_compact(
    const int* __restrict__ vis_b, int* jl_sh, int* wsum, int tid)
{
    const int lane = tid & 31, w = tid >> 5;
    const int4 v = ((const int4*)vis_b)[tid];        // elems 4t..4t+3
    const int a0 = (v.x == 0), a1 = (v.y == 0), a2 = (v.z == 0), a3 = (v.w == 0);
    const int cnt = a0 + a1 + a2 + a3;
    int s = cnt;
#pragma unroll
    for (int o = 1; o < 32; o <<= 1) {
        int x = __shfl_up_sync(0xffffffffu, s, o);
        if (lane >= o) s += x;
    }
    if (lane == 31) wsum[w] = s;
    __syncthreads();
    int nact = 0, base = 0;
#pragma unroll
    for (int k = 0; k < 8; k++) {
        int t = wsum[k];
        nact += t;
        if (k < w) base += t;
    }
    int off = base + s - cnt;                        // exclusive prefix
    const int j4 = 4 * tid;
    if (a0) jl_sh[off++] = j4;
    if (a1) jl_sh[off++] = j4 + 1;
    if (a2) jl_sh[off++] = j4 + 2;
    if (a3) jl_sh[off++] = j4 + 3;
    __syncthreads();
    return nact;
}

// ---------------------------------------------------------------------------
// Pass 1 over ACTIVE nodes only, compacted index space (no global jlist):
// for idx < nact, n = jl_sh[idx]:
//   ai[n] = E[n] @ Wi^T ;  ajbTc[h][idx] = E[n] @ Wj^T + b1.
// Grid = B*N/8 = 256 blocks (blocks past nact exit after the cheap
// compaction), 256 threads. Tail columns of ajbTc are left unwritten —
// pass2 provably discards them.
// ---------------------------------------------------------------------------
__global__ __launch_bounds__(256) void pass1c_kernel(
    const float* __restrict__ E, const float* __restrict__ W1,
    const float* __restrict__ b1, const int* __restrict__ visited)
{
    __shared__ float Esh[8][32];
    __shared__ float Wc[32][132];
    __shared__ int jl_sh[N_];
    __shared__ int wsum[8];

    const int tid = threadIdx.x;
    const int b = blockIdx.x >> 7;
    const int idx0 = (blockIdx.x & 127) * 8;

    const int nact = block_compact(visited + b * N_, jl_sh, wsum, tid);
    if (idx0 >= nact) return;                 // whole block inactive

    const int r = tid >> 5;
    const int ob = (tid & 31) * 4;
    const int idx = idx0 + r;
    const int n = jl_sh[(idx < nact) ? idx : (nact - 1)];   // clamp partials

    float acc[4] = {0.f, 0.f, 0.f, 0.f};

    for (int dc = 0; dc < D_; dc += 32) {
        __syncthreads();
        {
            int rr = tid >> 5, dd = tid & 31;
            int ii = idx0 + rr;
            int nn = jl_sh[(ii < nact) ? ii : (nact - 1)];
            Esh[rr][dd] = E[(b * N_ + nn) * D_ + dc + dd];
        }
#pragma unroll
        for (int k = tid; k < 32 * 128; k += 256) {
            int o = k >> 5, dd = k & 31;
            float v = (o < H_) ? W1[o * (2 * D_) + dc + dd]
                               : W1[(o - H_) * (2 * D_) + D_ + dc + dd];
            Wc[dd][o] = v;
        }
        __syncthreads();
#pragma unroll
        for (int dd = 0; dd < 32; dd++) {
            const float e = Esh[r][dd];                     // warp broadcast
            const float4 w4 = *(const float4*)&Wc[dd][ob];  // conflict-free
            acc[0] += e * w4.x;  acc[1] += e * w4.y;
            acc[2] += e * w4.z;  acc[3] += e * w4.w;
        }
    }

    if (idx < nact) {                          // guard partial blocks
        if (ob < H_) {
            *(float4*)&g_ai[(b * N_ + n) * H_ + ob] =
                make_float4(acc[0], acc[1], acc[2], acc[3]);
        } else {
            const int h0 = ob - H_;
#pragma unroll
            for (int k = 0; k < 4; k++)
                g_ajbTc[(b * H_ + h0 + k) * N_ + idx] = acc[k] + b1[h0 + k];
        }
    }
}

// ---------------------------------------------------------------------------
// Pass 2 (proven 20.7us body): compacted columns + cp.async double-buffered
// half-tile pipeline; in-register softmax; scatter via LOCAL jl_sh.
// Tail columns [nact, npad) may contain garbage: their accumulators are
// unconditionally replaced by -1e9 via the jc<nact mask before any use.
// Grid = B*N/8 = 256 blocks, 256 thr = 8 warps, warp w owns row i_base+w.
// ---------------------------------------------------------------------------
__global__ __launch_bounds__(256) void pass2_kernel(
    const int* __restrict__ visited,
    const float* __restrict__ W2, const float* __restrict__ b2,
    float* __restrict__ out)
{
    __shared__ float buf[2][32][128];       // 32 KB
    __shared__ float2 pk[8][H_];            // 4 KB: (ai[i], w2[h])
    __shared__ int jl_sh[N_];               // 4 KB
    __shared__ int wsum[8];

    const int tid = threadIdx.x;
    const int w = tid >> 5, lane = tid & 31;
    const int b = blockIdx.x >> 7;
    const int i_base = (blockIdx.x & 127) * 8;
    const int i = i_base + w;

    const int nact = block_compact(visited + b * N_, jl_sh, wsum, tid);
    const int T = (nact + 127) >> 7;
    const int C = 2 * T;                    // block-uniform chunk count
    const float* base = &g_ajbTc[(b * H_) * N_];

#pragma unroll
    for (int k = tid; k < 8 * H_; k += 256) {
        int wi = k >> 6, h = k & 63;
        pk[wi][h] = make_float2(g_ai[(b * N_ + i_base + wi) * H_ + h], W2[h]);
    }

    const bool vi = visited[b * N_ + i] != 0;      // warp-uniform
    float* orow = out + (size_t)(b * N_ + i) * N_;
    if (vi) {
        const float4 uni = make_float4(1.f / N_, 1.f / N_, 1.f / N_, 1.f / N_);
#pragma unroll
        for (int t = 0; t < 8; t++) *(float4*)&orow[t * 128 + lane * 4] = uni;
    } else {
        const float4 z = make_float4(0.f, 0.f, 0.f, 0.f);
#pragma unroll
        for (int t = 0; t < 8; t++) *(float4*)&orow[t * 128 + lane * 4] = z;
    }

    // Prologue: stage chunk 0 (tile 0, h 0..31) into buf[0].
    if (C > 0) {
#pragma unroll
        for (int r = 0; r < 4; r++) {
            int k = tid + r * 256;
            int h = k >> 5, c4 = k & 31;
            cp_async16(&buf[0][h][c4 * 4], base + h * N_ + c4 * 4);
        }
    }
    CP_COMMIT();

    float a[8][4] = {};

#pragma unroll
    for (int c = 0; c < 16; c++) {
        if (c < C) {                               // block-uniform
            __syncthreads();                       // chunk c-1 compute done
            if (c + 1 < C) {
                const int t1 = (c + 1) >> 1, hh1 = ((c + 1) & 1) * 32;
                float (*nb)[128] = buf[(c + 1) & 1];
                const float* src = base + t1 * 128 + hh1 * N_;
#pragma unroll
                for (int r = 0; r < 4; r++) {
                    int k = tid + r * 256;
                    int h = k >> 5, c4 = k & 31;
                    cp_async16(&nb[h][c4 * 4], src + h * N_ + c4 * 4);
                }
            }
            CP_COMMIT();
            CP_WAIT1();                            // chunk c complete
            __syncthreads();

            if (!vi) {
                const int t = c >> 1, hh = (c & 1) * 32;
                const float (*cb)[128] = buf[c & 1];
                float s0 = 0.f, s1 = 0.f, s2 = 0.f, s3 = 0.f;
#pragma unroll 8
                for (int h = 0; h < 32; h++) {
                    const float2 cc = pk[w][hh + h];              // LDS.64 bcast
                    const float4 v = *(const float4*)&cb[h][lane * 4];
                    s0 += fmaxf(cc.x + v.x, 0.f) * cc.y;
                    s1 += fmaxf(cc.x + v.y, 0.f) * cc.y;
                    s2 += fmaxf(cc.x + v.z, 0.f) * cc.y;
                    s3 += fmaxf(cc.x + v.w, 0.f) * cc.y;
                }
                a[t][0] += s0; a[t][1] += s1; a[t][2] += s2; a[t][3] += s3;
            }
        }
    }

    if (vi) return;

    // ---- softmax over active columns (jc < nact), in registers ----
    const float bb = b2[0];
    float m = -3.4e38f;
#pragma unroll
    for (int t = 0; t < 8; t++)
#pragma unroll
        for (int k = 0; k < 4; k++) {
            const int jc = t * 128 + lane * 4 + k;
            float e = (jc < nact) ? (a[t][k] + bb) : -1.0e9f;
            a[t][k] = e;
            m = fmaxf(m, e);
        }
#pragma unroll
    for (int o = 16; o > 0; o >>= 1)
        m = fmaxf(m, __shfl_xor_sync(0xffffffffu, m, o));

    float sum = 0.f;
#pragma unroll
    for (int t = 0; t < 8; t++)
#pragma unroll
        for (int k = 0; k < 4; k++) {
            const float p = __expf(a[t][k] - m);
            a[t][k] = p; sum += p;
        }
#pragma unroll
    for (int o = 16; o > 0; o >>= 1)
        sum += __shfl_xor_sync(0xffffffffu, sum, o);

    const float inv = 1.f / sum;
#pragma unroll
    for (int t = 0; t < 8; t++)
#pragma unroll
        for (int k = 0; k < 4; k++) {
            const int jc = t * 128 + lane * 4 + k;
            if (jc < nact) orow[jl_sh[jc]] = a[t][k] * inv;
        }
}

extern "C" void kernel_launch(void* const* d_in, const int* in_sizes, int n_in,
                              void* d_out, int out_size) {
    const float* E  = (const float*)d_in[0];
    const int* vis  = (const int*)d_in[1];   // jax bool -> int32 in harness
    // d_in[2] = remaining_capacity: unused by the reference.
    const float* W1 = (const float*)d_in[3];
    const float* b1 = (const float*)d_in[4];
    const float* W2 = (const float*)d_in[5];
    const float* b2 = (const float*)d_in[6];
    float* out      = (float*)d_out;

    pass1c_kernel<<<B_ * (N_ / 8), 256>>>(E, W1, b1, vis);
    pass2_kernel<<<B_ * (N_ / 8), 256>>>(vis, W2, b2, out);
}